// round 3
// baseline (speedup 1.0000x reference)
#include <cuda_runtime.h>

// Problem: SlidingAttnScoreCache — one decode step of a sliding cache at capacity.
// B=8, H=8, S=1024, D=64. Inputs (metadata order):
//  0 q_cache (B,H,S,D) f32      1 k_cache   2 v_cache
//  3 attn_score_cache (B,H,S,S) f32
//  4 q (B,H,1,D)  5 k  6 v
//  7 q_t (B,H,1,S)  8 k_t (B,H,S,1)  9 current_seq_len (scalar int)
// Output: concat[q_cache', k_cache', v_cache', attn_score_cache'] as f32.

#define Bc 8
#define Hc 8
#define Sc 1024
#define Dc 64
#define D4c (Dc / 4)            // 16 float4 per (b,h,s) row
#define N_CACHE (Bc * Hc * Sc * Dc)       // 4,194,304 floats per qkv cache
#define N4_CACHE (N_CACHE / 4)            // 1,048,576 float4
#define BH (Bc * Hc)

// ---------------------------------------------------------------------------
// Kernel A: q/k/v caches.  out[b,h,s,d] = (s==c) ? new[b,h,d]
//                                        : in[b,h, min(s+shift, S-1), d]
// shift = (csl >= S-1) ? 1 : 0;  c = min(csl, S-1).
// One float4 per thread, 3 caches concatenated in one grid.
// ---------------------------------------------------------------------------
__global__ __launch_bounds__(256)
void qkv_shift_kernel(const float4* __restrict__ qc,
                      const float4* __restrict__ kc,
                      const float4* __restrict__ vc,
                      const float4* __restrict__ qn,
                      const float4* __restrict__ kn,
                      const float4* __restrict__ vn,
                      const int* __restrict__ csl_ptr,
                      float4* __restrict__ out)
{
    int idx = blockIdx.x * blockDim.x + threadIdx.x;   // 0 .. 3*N4_CACHE-1
    if (idx >= 3 * N4_CACHE) return;

    int which = idx / N4_CACHE;                        // 0=q,1=k,2=v
    int r     = idx - which * N4_CACHE;                // index within one cache

    const float4* in = (which == 0) ? qc : (which == 1) ? kc : vc;
    const float4* nv = (which == 0) ? qn : (which == 1) ? kn : vn;

    int csl   = *csl_ptr;
    int shift = (csl >= Sc - 1) ? 1 : 0;
    int c     = (csl < Sc - 1) ? csl : (Sc - 1);

    int d4 = r & (D4c - 1);          // r % 16
    int s  = (r >> 4) & (Sc - 1);    // (r/16) % 1024
    int bh = r >> 14;                // r / (1024*16)

    float4 val;
    if (s == c) {
        val = nv[bh * D4c + d4];
    } else {
        int ss = s + shift; if (ss > Sc - 1) ss = Sc - 1;
        val = in[(bh * Sc + ss) * D4c + d4];
    }
    out[idx] = val;
}

// ---------------------------------------------------------------------------
// Kernel B: attn score cache.
//   shift = (csl >= S-1) ? 2 : 0;  c = min(csl, S-1)
//   out[s,t] = (t==c) ? k_t[s]
//            : (s==c) ? q_t[t]
//            : in[min(s+shift,S-1), min(t+shift,S-1)]
// One row (1024 floats) per 256-thread block; one float4 store per thread.
// shift==2 load path: two 8B-aligned float2 loads (t is even).
// ---------------------------------------------------------------------------
__global__ __launch_bounds__(256)
void attn_shift_kernel(const float* __restrict__ a_in,
                       const float* __restrict__ q_t,
                       const float* __restrict__ k_t,
                       const int* __restrict__ csl_ptr,
                       float4* __restrict__ out4)
{
    int row = blockIdx.x;            // 0 .. BH*S-1
    int s   = row & (Sc - 1);
    int bh  = row >> 10;
    int t   = threadIdx.x << 2;      // column of first element: 0,4,...,1020

    int csl   = *csl_ptr;
    int shift = (csl >= Sc - 1) ? 2 : 0;
    int c     = (csl < Sc - 1) ? csl : (Sc - 1);

    float4 val;

    if (s == c) {
        // row c: q_t, with column c patched to k_t[c]
        const float* qr = q_t + bh * Sc;
        val = *reinterpret_cast<const float4*>(qr + t);
        if (c >= t && c < t + 4)
            reinterpret_cast<float*>(&val)[c - t] = k_t[bh * Sc + c];
    } else if (shift == 0) {
        // no shift: plain copy of this row, column c patched to k_t[s]
        const float* ir = a_in + ((long)(bh * Sc + s)) * Sc;
        val = *reinterpret_cast<const float4*>(ir + t);
        if (c >= t && c < t + 4)
            reinterpret_cast<float*>(&val)[c - t] = k_t[bh * Sc + s];
    } else {
        // shift == 2, c == S-1
        int ss = s + 2; if (ss > Sc - 1) ss = Sc - 1;
        const float* ir = a_in + ((long)(bh * Sc + ss)) * Sc;
        if (t + 6 <= Sc) {
            // cols t..t+3 <- in cols t+2..t+5 (all < S), none equals c
            float2 a = *reinterpret_cast<const float2*>(ir + t + 2);
            float2 b = *reinterpret_cast<const float2*>(ir + t + 4);
            val.x = a.x; val.y = a.y; val.z = b.x; val.w = b.y;
        } else {
            // t == S-4 (1020): cols 1020,1021,1022,1023
            val.x = ir[Sc - 2];          // min(1022, S-1)
            val.y = ir[Sc - 1];          // min(1023, S-1)
            val.z = ir[Sc - 1];          // min(1024, S-1) clamped
            val.w = k_t[bh * Sc + s];    // col S-1 == c
        }
    }

    out4[(long)row * (Sc / 4) + threadIdx.x] = val;
}

extern "C" void kernel_launch(void* const* d_in, const int* in_sizes, int n_in,
                              void* d_out, int out_size)
{
    const float4* qc  = (const float4*)d_in[0];
    const float4* kc  = (const float4*)d_in[1];
    const float4* vc  = (const float4*)d_in[2];
    const float*  ac  = (const float*) d_in[3];
    const float4* qn  = (const float4*)d_in[4];
    const float4* kn  = (const float4*)d_in[5];
    const float4* vn  = (const float4*)d_in[6];
    const float*  qt  = (const float*) d_in[7];
    const float*  kt  = (const float*) d_in[8];
    const int*    csl = (const int*)   d_in[9];

    float4* out4 = (float4*)d_out;

    // q/k/v caches: 3 * 1,048,576 float4
    {
        int total = 3 * N4_CACHE;
        int threads = 256;
        int blocks = (total + threads - 1) / threads;
        qkv_shift_kernel<<<blocks, threads>>>(qc, kc, vc, qn, kn, vn, csl, out4);
    }

    // attn cache: starts at float4 offset 3*N4_CACHE
    {
        int blocks = BH * Sc;              // 65536 rows
        attn_shift_kernel<<<blocks, 256>>>(ac, qt, kt, csl, out4 + 3 * N4_CACHE);
    }
}

// round 4
// speedup vs baseline: 1.0527x; 1.0527x over previous
#include <cuda_runtime.h>

// SlidingAttnScoreCache — one decode step of a sliding cache at capacity.
// B=8, H=8, S=1024, D=64. Inputs (metadata order):
//  0 q_cache (B,H,S,D) f32   1 k_cache   2 v_cache
//  3 attn_score_cache (B,H,S,S) f32
//  4 q (B,H,1,D)  5 k  6 v
//  7 q_t (B,H,1,S)  8 k_t (B,H,S,1)  9 current_seq_len (scalar int)
// Output: concat[q_cache', k_cache', v_cache', attn_score_cache'] f32.

#define Bc 8
#define Hc 8
#define Sc 1024
#define Dc 64
#define D4c (Dc / 4)                      // 16 float4 per (b,h,s) row
#define N_CACHE (Bc * Hc * Sc * Dc)      // 4,194,304 floats per qkv cache
#define N4_CACHE (N_CACHE / 4)           // 1,048,576 float4
#define BH (Bc * Hc)
#define ATTN_BLOCKS (BH * Sc)            // 65536 rows, one per block
#define QKV_BLOCKS (3 * N4_CACHE / 256)  // 12288

// ---------------------------------------------------------------------------
// Fused kernel.
//  blocks [0, ATTN_BLOCKS):        attn score cache, one 1024-float row/block
//  blocks [ATTN_BLOCKS, +QKV):     q/k/v caches, one float4/thread
//
// attn semantics (shift applied twice at capacity):
//   shift = (csl >= S-1) ? 2 : 0;  c = min(csl, S-1)
//   out[s,t] = (t==c) ? k_t[s] : (s==c) ? q_t[t]
//            : in[min(s+shift,S-1), min(t+shift,S-1)]
// qkv semantics:
//   shift = (csl >= S-1) ? 1 : 0
//   out[s] = (s==c) ? new : in[min(s+shift, S-1)]
// ---------------------------------------------------------------------------
__global__ __launch_bounds__(256)
void sliding_cache_fused(const float4* __restrict__ qc,
                         const float4* __restrict__ kc,
                         const float4* __restrict__ vc,
                         const float*  __restrict__ a_in,
                         const float4* __restrict__ qn,
                         const float4* __restrict__ kn,
                         const float4* __restrict__ vn,
                         const float*  __restrict__ q_t,
                         const float*  __restrict__ k_t,
                         const int*    __restrict__ csl_ptr,
                         float4* __restrict__ out4)
{
    int blk = blockIdx.x;
    int tid = threadIdx.x;
    int csl = *csl_ptr;                      // uniform, L1/L2 hit

    if (blk < ATTN_BLOCKS) {
        // ---------------- attn score cache ----------------
        __shared__ float sm[Sc];
        int s  = blk & (Sc - 1);
        int bh = blk >> 10;
        int t  = tid << 2;                   // first output column
        int shift = (csl >= Sc - 1) ? 2 : 0;
        int c     = (csl < Sc - 1) ? csl : (Sc - 1);

        float4 val;
        if (s == c) {
            // row c <- q_t, column c patched to k_t[c]
            val = __ldcs(reinterpret_cast<const float4*>(q_t + bh * Sc) + tid);
            if (c >= t && c < t + 4)
                reinterpret_cast<float*>(&val)[c - t] = k_t[bh * Sc + c];
        } else if (shift == 0) {
            // plain row copy, column c patched to k_t[s]
            const float* ir = a_in + (long)(bh * Sc + s) * Sc;
            val = __ldcs(reinterpret_cast<const float4*>(ir) + tid);
            if (c >= t && c < t + 4)
                reinterpret_cast<float*>(&val)[c - t] = k_t[bh * Sc + s];
        } else {
            // shift == 2 path (c == S-1): out[s,t..t+3] = in[s+2, t+2..t+5]
            int ss = s + 2; if (ss > Sc - 1) ss = Sc - 1;
            const float4* ir4 =
                reinterpret_cast<const float4*>(a_in + (long)(bh * Sc + ss) * Sc);
            // stage source row aligned into smem
            reinterpret_cast<float4*>(sm)[tid] = __ldcs(ir4 + tid);
            __syncthreads();
            if (t < Sc - 4) {
                float2 a = *reinterpret_cast<const float2*>(sm + t + 2);
                float2 b = *reinterpret_cast<const float2*>(sm + t + 4);
                val.x = a.x; val.y = a.y; val.z = b.x; val.w = b.y;
            } else {
                // t == 1020: cols 1022, 1023, clamp(1024)->1023, col 1023 == c
                val.x = sm[Sc - 2];
                val.y = sm[Sc - 1];
                val.z = sm[Sc - 1];
                val.w = k_t[bh * Sc + s];
            }
        }
        __stcs(out4 + (long)(3 * N4_CACHE) + (long)blk * (Sc / 4) + tid, val);
    } else {
        // ---------------- q/k/v caches ----------------
        int idx = (blk - ATTN_BLOCKS) * 256 + tid;    // 0 .. 3*N4_CACHE-1
        int which = idx / N4_CACHE;                   // 0=q,1=k,2=v
        int r     = idx - which * N4_CACHE;

        const float4* in = (which == 0) ? qc : (which == 1) ? kc : vc;
        const float4* nv = (which == 0) ? qn : (which == 1) ? kn : vn;

        int shift = (csl >= Sc - 1) ? 1 : 0;
        int c     = (csl < Sc - 1) ? csl : (Sc - 1);

        int d4 = r & (D4c - 1);
        int s  = (r >> 4) & (Sc - 1);
        int bh = r >> 14;

        float4 val;
        if (s == c) {
            val = nv[bh * D4c + d4];
        } else {
            int ss = s + shift; if (ss > Sc - 1) ss = Sc - 1;
            val = __ldcs(in + (long)(bh * Sc + ss) * D4c + d4);
        }
        __stcs(out4 + idx, val);
    }
}

extern "C" void kernel_launch(void* const* d_in, const int* in_sizes, int n_in,
                              void* d_out, int out_size)
{
    const float4* qc  = (const float4*)d_in[0];
    const float4* kc  = (const float4*)d_in[1];
    const float4* vc  = (const float4*)d_in[2];
    const float*  ac  = (const float*) d_in[3];
    const float4* qn  = (const float4*)d_in[4];
    const float4* kn  = (const float4*)d_in[5];
    const float4* vn  = (const float4*)d_in[6];
    const float*  qt  = (const float*) d_in[7];
    const float*  kt  = (const float*) d_in[8];
    const int*    csl = (const int*)   d_in[9];

    float4* out4 = (float4*)d_out;

    sliding_cache_fused<<<ATTN_BLOCKS + QKV_BLOCKS, 256>>>(
        qc, kc, vc, ac, qn, kn, vn, qt, kt, csl, out4);
}

// round 5
// speedup vs baseline: 1.1646x; 1.1064x over previous
#include <cuda_runtime.h>

// SlidingAttnScoreCache — one decode step of a sliding cache at capacity.
// B=8, H=8, S=1024, D=64.
//  0 q_cache (B,H,S,D) f32   1 k_cache   2 v_cache
//  3 attn_score_cache (B,H,S,S) f32
//  4 q (B,H,1,D)  5 k  6 v
//  7 q_t (B,H,1,S)  8 k_t (B,H,S,1)  9 current_seq_len (scalar int)
// Output: concat[q_cache', k_cache', v_cache', attn_score_cache'] f32.

#define Bc 8
#define Hc 8
#define Sc 1024
#define Dc 64
#define D4c (Dc / 4)
#define N_CACHE (Bc * Hc * Sc * Dc)      // 4,194,304 floats per qkv cache
#define N4_CACHE (N_CACHE / 4)           // 1,048,576 float4
#define BH (Bc * Hc)
#define ATTN_BLOCKS (BH * Sc / 2)        // 32768 blocks, 2 rows each
#define QKV_BLOCKS (3 * N4_CACHE / 512)  // 6144 blocks, 2 float4/thread

// Assemble out[s, 4t..4t+3] = in[ss, 4t+2..4t+5] from the aligned load A_t,
// using shuffles for the cross-thread pair; lane31 uses ext (predicated 8B
// load); tid==255 clamps col 1024 -> 1023 and sets col 1023 (== c) to k_t[s].
__device__ __forceinline__
float4 shift2_assemble(float4 A, float2 ext, int tid, int lane, float ktv)
{
    float nx = __shfl_down_sync(0xffffffffu, A.x, 1);
    float ny = __shfl_down_sync(0xffffffffu, A.y, 1);
    if (lane == 31) { nx = ext.x; ny = ext.y; }
    float4 v;
    v.x = A.z; v.y = A.w; v.z = nx; v.w = ny;
    if (tid == 255) { v.z = A.w; v.w = ktv; }
    return v;
}

__global__ __launch_bounds__(256)
void sliding_cache_fused(const float4* __restrict__ qc,
                         const float4* __restrict__ kc,
                         const float4* __restrict__ vc,
                         const float*  __restrict__ a_in,
                         const float4* __restrict__ qn,
                         const float4* __restrict__ kn,
                         const float4* __restrict__ vn,
                         const float*  __restrict__ q_t,
                         const float*  __restrict__ k_t,
                         const int*    __restrict__ csl_ptr,
                         float4* __restrict__ out4)
{
    int blk  = blockIdx.x;
    int tid  = threadIdx.x;
    int lane = tid & 31;
    int csl  = *csl_ptr;

    if (blk < ATTN_BLOCKS) {
        // ---------------- attn score cache: rows 2*blk, 2*blk+1 ----------------
        int row0 = blk * 2;
        int s0   = row0 & (Sc - 1);
        int s1   = s0 + 1;
        int bh   = row0 >> 10;
        int t    = tid << 2;
        int shift = (csl >= Sc - 1) ? 2 : 0;
        int c     = (csl < Sc - 1) ? csl : (Sc - 1);

        float4* outp = out4 + (long)(3 * N4_CACHE);
        long o0 = (long)row0 * (Sc / 4) + tid;

        if (shift == 2) {
            // c == S-1 here; s0 is even so s0 != c; s1 may be c (last pair).
            int ss0 = s0 + 2; if (ss0 > Sc - 1) ss0 = Sc - 1;
            int ss1 = s1 + 2; if (ss1 > Sc - 1) ss1 = Sc - 1;
            const float* ir0 = a_in + (long)(bh * Sc + ss0) * Sc;
            const float* ir1 = a_in + (long)(bh * Sc + ss1) * Sc;

            // batch all loads (2 independent LDG.128 + predicated 8B tails)
            float4 A0 = __ldcs(reinterpret_cast<const float4*>(ir0) + tid);
            float4 A1 = __ldcs(reinterpret_cast<const float4*>(ir1) + tid);
            float2 e0, e1;
            if (lane == 31 && tid != 255) {
                e0 = *reinterpret_cast<const float2*>(ir0 + t + 4);
                e1 = *reinterpret_cast<const float2*>(ir1 + t + 4);
            }
            float kt0 = k_t[bh * Sc + s0];
            float kt1 = k_t[bh * Sc + s1];

            float4 v0 = shift2_assemble(A0, e0, tid, lane, kt0);
            float4 v1 = shift2_assemble(A1, e1, tid, lane, kt1);

            if (s1 == c) {
                // row c <- q_t, column c (tid 255, elem w) <- k_t[c]
                v1 = __ldcs(reinterpret_cast<const float4*>(q_t + bh * Sc) + tid);
                if (c >= t && c < t + 4)
                    reinterpret_cast<float*>(&v1)[c - t] = kt1;
            }
            __stcs(outp + o0, v0);
            __stcs(outp + o0 + (Sc / 4), v1);
        } else {
            // shift == 0: plain row copies with patches
            const float* base = a_in + (long)(bh * Sc) * Sc;
            float4 v0, v1;
            if (s0 == c) {
                v0 = __ldcs(reinterpret_cast<const float4*>(q_t + bh * Sc) + tid);
                if (c >= t && c < t + 4)
                    reinterpret_cast<float*>(&v0)[c - t] = k_t[bh * Sc + c];
            } else {
                v0 = __ldcs(reinterpret_cast<const float4*>(base + (long)s0 * Sc) + tid);
                if (c >= t && c < t + 4)
                    reinterpret_cast<float*>(&v0)[c - t] = k_t[bh * Sc + s0];
            }
            if (s1 == c) {
                v1 = __ldcs(reinterpret_cast<const float4*>(q_t + bh * Sc) + tid);
                if (c >= t && c < t + 4)
                    reinterpret_cast<float*>(&v1)[c - t] = k_t[bh * Sc + c];
            } else {
                v1 = __ldcs(reinterpret_cast<const float4*>(base + (long)s1 * Sc) + tid);
                if (c >= t && c < t + 4)
                    reinterpret_cast<float*>(&v1)[c - t] = k_t[bh * Sc + s1];
            }
            __stcs(outp + o0, v0);
            __stcs(outp + o0 + (Sc / 4), v1);
        }
    } else {
        // ---------------- q/k/v caches: 2 float4 per thread ----------------
        int base = (blk - ATTN_BLOCKS) * 512;            // 512-aligned, never spans caches
        int which = base / N4_CACHE;                     // 0=q,1=k,2=v
        const float4* in = (which == 0) ? qc : (which == 1) ? kc : vc;
        const float4* nv = (which == 0) ? qn : (which == 1) ? kn : vn;

        int shift = (csl >= Sc - 1) ? 1 : 0;
        int c     = (csl < Sc - 1) ? csl : (Sc - 1);

        int r0 = (base - which * N4_CACHE) + tid;
        int r1 = r0 + 256;

        // element 0
        int d40 = r0 & (D4c - 1), sA = (r0 >> 4) & (Sc - 1), bh0 = r0 >> 14;
        int d41 = r1 & (D4c - 1), sB = (r1 >> 4) & (Sc - 1), bh1 = r1 >> 14;

        int ssA = sA + shift; if (ssA > Sc - 1) ssA = Sc - 1;
        int ssB = sB + shift; if (ssB > Sc - 1) ssB = Sc - 1;

        // batch both loads
        float4 vA = (sA == c) ? nv[bh0 * D4c + d40]
                              : __ldcs(in + (long)(bh0 * Sc + ssA) * D4c + d40);
        float4 vB = (sB == c) ? nv[bh1 * D4c + d41]
                              : __ldcs(in + (long)(bh1 * Sc + ssB) * D4c + d41);

        __stcs(out4 + base + tid, vA);
        __stcs(out4 + base + 256 + tid, vB);
    }
}

extern "C" void kernel_launch(void* const* d_in, const int* in_sizes, int n_in,
                              void* d_out, int out_size)
{
    const float4* qc  = (const float4*)d_in[0];
    const float4* kc  = (const float4*)d_in[1];
    const float4* vc  = (const float4*)d_in[2];
    const float*  ac  = (const float*) d_in[3];
    const float4* qn  = (const float4*)d_in[4];
    const float4* kn  = (const float4*)d_in[5];
    const float4* vn  = (const float4*)d_in[6];
    const float*  qt  = (const float*) d_in[7];
    const float*  kt  = (const float*) d_in[8];
    const int*    csl = (const int*)   d_in[9];

    float4* out4 = (float4*)d_out;

    sliding_cache_fused<<<ATTN_BLOCKS + QKV_BLOCKS, 256>>>(
        qc, kc, vc, ac, qn, kn, vn, qt, kt, csl, out4);
}